// round 1
// baseline (speedup 1.0000x reference)
#include <cuda_runtime.h>
#include <math.h>

// Problem constants
#define BB   4
#define SS   2048
#define EE   256
#define HH   8
#define DDIM 32
#define WWIN 33
#define PADW 16
#define KKEY 2016        // S - W + 1
#define NBH  32          // B*H

// Attention tiling
#define TQ   128
#define TK   64
#define QSR  (TQ + 32)   // 160 q rows incl. halo
#define KSR  (TK + 32)   // 96 k rows incl. halo
#define LDQ  33          // padded row stride for q/k/vs tiles
#define LDG  97          // padded row stride for G
#define LDP  65          // padded row stride for P
#define NTH  512

// Shared memory layout (floats)
#define OFF_QS  0
#define OFF_KS  (OFF_QS + QSR * LDQ)        // 5280
#define OFF_VS  (OFF_KS + KSR * LDQ)        // 8448
#define OFF_G   (OFF_VS + TK  * LDQ)        // 10560
#define OFF_P   (OFF_G  + QSR * LDG)        // 26080
#define OFF_DEN (OFF_P  + TQ  * LDP)        // 34400
#define SMEM_FLOATS (OFF_DEN + TQ)          // 34528
#define SMEM_BYTES  (SMEM_FLOATS * 4)       // 138112 B

// Scratch (device globals: no runtime allocation allowed)
__device__ float g_q[NBH * SS * DDIM];
__device__ float g_k[NBH * SS * DDIM];
__device__ float g_v[NBH * SS * DDIM];
__device__ float g_vsum[NBH * KKEY * DDIM];

// ---------------------------------------------------------------------------
// Kernel 1: fused QKV projection.  out[8192, 768] = x[8192,256] @ [Wq|Wk|Wv]
// + bias, scattered into per-head [bh][s][d] layout.
// ---------------------------------------------------------------------------
__global__ __launch_bounds__(256) void proj_kernel(
    const float* __restrict__ x,
    const float* __restrict__ Wq, const float* __restrict__ bq,
    const float* __restrict__ Wk, const float* __restrict__ bk,
    const float* __restrict__ Wv, const float* __restrict__ bv)
{
    __shared__ float xs[64][17];
    __shared__ float ws[16][65];

    int tid = threadIdx.x;            // 256 threads
    int m0  = blockIdx.y * 64;        // row tile
    int n0  = blockIdx.x * 64;        // col tile (within 768)
    int msel = n0 >> 8;               // 0=q, 1=k, 2=v
    const float* Wsel = (msel == 0) ? Wq : (msel == 1) ? Wk : Wv;
    const float* bsel = (msel == 0) ? bq : (msel == 1) ? bk : bv;
    int ncol0 = n0 & 255;

    int ty = tid >> 4;                // 0..15 (m dir)
    int tx = tid & 15;                // 0..15 (n dir)

    float acc[4][4];
#pragma unroll
    for (int i = 0; i < 4; i++)
#pragma unroll
        for (int j = 0; j < 4; j++) acc[i][j] = 0.f;

    for (int k0 = 0; k0 < EE; k0 += 16) {
        {   // load x tile 64x16 (float4 per thread)
            int row = tid >> 2;
            int kk  = (tid & 3) * 4;
            float4 xv = *reinterpret_cast<const float4*>(
                &x[(size_t)(m0 + row) * EE + k0 + kk]);
            xs[row][kk]     = xv.x; xs[row][kk + 1] = xv.y;
            xs[row][kk + 2] = xv.z; xs[row][kk + 3] = xv.w;
        }
        {   // load W tile 16x64
            int kk = tid >> 4;
            int nn = (tid & 15) * 4;
            float4 wv = *reinterpret_cast<const float4*>(
                &Wsel[(size_t)(k0 + kk) * EE + ncol0 + nn]);
            ws[kk][nn]     = wv.x; ws[kk][nn + 1] = wv.y;
            ws[kk][nn + 2] = wv.z; ws[kk][nn + 3] = wv.w;
        }
        __syncthreads();
#pragma unroll
        for (int kk = 0; kk < 16; kk++) {
            float a[4], b[4];
#pragma unroll
            for (int i = 0; i < 4; i++) a[i] = xs[ty * 4 + i][kk];
#pragma unroll
            for (int j = 0; j < 4; j++) b[j] = ws[kk][tx * 4 + j];
#pragma unroll
            for (int i = 0; i < 4; i++)
#pragma unroll
                for (int j = 0; j < 4; j++) acc[i][j] += a[i] * b[j];
        }
        __syncthreads();
    }

    float* dst = (msel == 0) ? g_q : (msel == 1) ? g_k : g_v;
#pragma unroll
    for (int i = 0; i < 4; i++) {
        int m = m0 + ty * 4 + i;
        int b = m >> 11;              // / 2048
        int s = m & 2047;
#pragma unroll
        for (int j = 0; j < 4; j++) {
            int e = ncol0 + tx * 4 + j;
            int h = e >> 5;
            int d = e & 31;
            float val = acc[i][j] + bsel[e];
            dst[(((size_t)(b * HH + h) * SS + s) * DDIM) + d] = val;
        }
    }
}

// ---------------------------------------------------------------------------
// Kernel 2: vsum[bh][k][d] = sum_{w<33} v[bh][k+w][d]
// ---------------------------------------------------------------------------
__global__ void vsum_kernel()
{
    int idx = blockIdx.x * blockDim.x + threadIdx.x;
    const int total = NBH * KKEY * DDIM;
    if (idx >= total) return;
    int d  = idx & 31;
    int k  = (idx >> 5) % KKEY;
    int bh = idx / (DDIM * KKEY);
    const float* vp = &g_v[((size_t)bh * SS + k) * DDIM + d];
    float s = 0.f;
#pragma unroll
    for (int w = 0; w < WWIN; w++) s += vp[w * DDIM];
    g_vsum[idx] = s;
}

// ---------------------------------------------------------------------------
// Kernel 3: attention via Gram-diagonal reformulation + no-max softmax.
// One block per (q-tile of 128, bh). Loops over 32 key tiles of 64.
// ---------------------------------------------------------------------------
__global__ __launch_bounds__(NTH, 1) void attn_kernel(float* __restrict__ out)
{
    extern __shared__ float sm[];
    float* qs  = sm + OFF_QS;   // [160][33]
    float* ks  = sm + OFF_KS;   // [96][33]
    float* vs  = sm + OFF_VS;   // [64][33]
    float* G   = sm + OFF_G;    // [160][97]
    float* P   = sm + OFF_P;    // [128][65]
    float* den = sm + OFF_DEN;  // [128]

    const float scale = 0.17677669529663687f;  // 1/sqrt(32)
    int tid = threadIdx.x;
    int q0  = blockIdx.x * TQ;
    int bh  = blockIdx.y;
    const float* qg = g_q    + (size_t)bh * SS   * DDIM;
    const float* kg = g_k    + (size_t)bh * SS   * DDIM;
    const float* vg = g_vsum + (size_t)bh * KKEY * DDIM;

    // Load q halo tile (rows q0-16 .. q0+143), zero-padded (matches jnp.pad)
    for (int idx = tid; idx < QSR * DDIM; idx += NTH) {
        int i = idx >> 5, d = idx & 31;
        int gq = q0 - PADW + i;
        qs[i * LDQ + d] = (gq >= 0 && gq < SS) ? qg[gq * DDIM + d] : 0.f;
    }
    if (tid < TQ) den[tid] = 0.f;

    // PV ownership: thread owns rows [qgrp*8 .. qgrp*8+7], column dcol
    int dcol = tid & 31;
    int qgrp = tid >> 5;     // 0..15
    float num[8];
#pragma unroll
    for (int r = 0; r < 8; r++) num[r] = 0.f;

    // Gram-GEMM thread coords: 32 (i-groups of 5) x 16 (j-groups of 6)
    int tx = tid & 15;
    int ty = tid >> 4;

    for (int kt = 0; kt < 32; kt++) {
        int k0 = kt * TK;
        __syncthreads();   // prev-iter P/vs consumed; also covers qs/den init

        // Load k halo tile + vsum tile
        for (int idx = tid; idx < KSR * DDIM; idx += NTH) {
            int j = idx >> 5, d = idx & 31;
            int gk = k0 + j;
            ks[j * LDQ + d] = (gk < SS) ? kg[gk * DDIM + d] : 0.f;
        }
        for (int idx = tid; idx < TK * DDIM; idx += NTH) {
            int j = idx >> 5, d = idx & 31;
            int gk = k0 + j;
            vs[j * LDQ + d] = (gk < KKEY) ? vg[gk * DDIM + d] : 0.f;
        }
        __syncthreads();

        // Phase B: G[i][j] = qs[i] . ks[j]   (160x96, D=32 contraction)
        {
            float acc[5][6];
#pragma unroll
            for (int i = 0; i < 5; i++)
#pragma unroll
                for (int j = 0; j < 6; j++) acc[i][j] = 0.f;
            int ib = ty * 5, jb = tx * 6;
#pragma unroll
            for (int d = 0; d < DDIM; d++) {
                float a[5], b[6];
#pragma unroll
                for (int i = 0; i < 5; i++) a[i] = qs[(ib + i) * LDQ + d];
#pragma unroll
                for (int j = 0; j < 6; j++) b[j] = ks[(jb + j) * LDQ + d];
#pragma unroll
                for (int i = 0; i < 5; i++)
#pragma unroll
                    for (int j = 0; j < 6; j++) acc[i][j] += a[i] * b[j];
            }
#pragma unroll
            for (int i = 0; i < 5; i++)
#pragma unroll
                for (int j = 0; j < 6; j++)
                    G[(ib + i) * LDG + (jb + j)] = acc[i][j];
        }
        __syncthreads();

        // Phase C: per-thread diagonal sliding-window sum + exp -> P
        // scores(qq,kk) = sum_{w<33} G[qq+w][kk+w]
        if (tid < TQ + TK - 1) {
            int qq, kk, len;
            if (tid < TQ) { qq = tid; kk = 0; len = min(TK, TQ - tid); }
            else          { qq = 0;  kk = tid - TQ + 1; len = TK - kk; }
            float s = 0.f;
#pragma unroll
            for (int w = 0; w < WWIN; w++)
                s += G[(qq + w) * LDG + (kk + w)];
            for (int t = 0; t < len; t++) {
                if (t) {
                    s += G[(qq + t + 32) * LDG + (kk + t + 32)]
                       - G[(qq + t - 1) * LDG + (kk + t - 1)];
                }
                float p = (k0 + kk + t < KKEY) ? __expf(s * scale) : 0.f;
                P[(qq + t) * LDP + (kk + t)] = p;
            }
        }
        __syncthreads();

        // Phase D: denominator + PV accumulation
        if (tid < TQ) {
            float dsum = 0.f;
#pragma unroll 8
            for (int j = 0; j < TK; j++) dsum += P[tid * LDP + j];
            den[tid] += dsum;
        }
        {
            int qb = qgrp * 8;
#pragma unroll 4
            for (int j = 0; j < TK; j++) {
                float vv = vs[j * LDQ + dcol];
#pragma unroll
                for (int r = 0; r < 8; r++)
                    num[r] += P[(qb + r) * LDP + j] * vv;
            }
        }
    }
    __syncthreads();

    // Write output: out[b, s, h*32+d]
    int b = bh >> 3, h = bh & 7;
    int qb = qgrp * 8;
#pragma unroll
    for (int r = 0; r < 8; r++) {
        int q = q0 + qb + r;
        out[((size_t)(b * SS + q) * EE) + h * DDIM + dcol] =
            num[r] / den[qb + r];
    }
}

// ---------------------------------------------------------------------------
extern "C" void kernel_launch(void* const* d_in, const int* in_sizes, int n_in,
                              void* d_out, int out_size)
{
    const float* x  = (const float*)d_in[0];
    const float* Wq = (const float*)d_in[1];
    const float* bq = (const float*)d_in[2];
    const float* Wk = (const float*)d_in[3];
    const float* bk = (const float*)d_in[4];
    const float* Wv = (const float*)d_in[5];
    const float* bv = (const float*)d_in[6];
    float* out = (float*)d_out;

    // 1) QKV projections: grid (768/64, 8192/64)
    {
        dim3 grid(12, 128);
        proj_kernel<<<grid, 256>>>(x, Wq, bq, Wk, bk, Wv, bv);
    }
    // 2) sliding V sums
    {
        const int total = NBH * KKEY * DDIM;
        vsum_kernel<<<(total + 255) / 256, 256>>>();
    }
    // 3) attention
    {
        cudaFuncSetAttribute(attn_kernel,
                             cudaFuncAttributeMaxDynamicSharedMemorySize,
                             SMEM_BYTES);
        dim3 grid(SS / TQ, NBH);   // (16, 32)
        attn_kernel<<<grid, NTH, SMEM_BYTES>>>(out);
    }
}